// round 10
// baseline (speedup 1.0000x reference)
#include <cuda_runtime.h>
#include <cstdint>

#define NB   8
#define CIN  128
#define COUT 256
#define KK   7
#define LL   16384
#define KC   896        // KK*CIN

#define BM 128
#define BN 128
#define BK 32
#define NITER 28        // KC/BK
#define THREADS 128
#define NSTAGE 2

// ---------------- device scratch (allocation-free rule: __device__ globals) ---
__device__ float g_xT[(size_t)NB * LL * CIN];   // x transposed to (n,l,c), tf32-rounded
__device__ float g_Bm[(size_t)COUT * KC];       // B[o][k*128+c], tf32-rounded
__device__ int   g_i64 = 1;                     // 1 if idx buffer is int64 (detect only clears)

// ---------------- helpers ----------------------------------------------------
__device__ __forceinline__ uint32_t smem_u32(const void* p){
    uint32_t a;
    asm("{ .reg .u64 t; cvta.to.shared.u64 t, %1; cvt.u32.u64 %0, t; }" : "=r"(a) : "l"(p));
    return a;
}
__device__ __forceinline__ float to_tf32(float f){
    uint32_t u; asm("cvt.rna.tf32.f32 %0, %1;" : "=r"(u) : "f"(f));
    return __uint_as_float(u);
}
__device__ __forceinline__ void cpa16(uint32_t dst, const void* src, int pbytes){
    asm volatile("cp.async.cg.shared.global [%0], [%1], 16, %2;"
        :: "r"(dst), "l"(src), "r"(pbytes) : "memory");
}
__device__ __forceinline__ uint32_t lds32(uint32_t a){
    uint32_t v; asm volatile("ld.shared.b32 %0, [%1];" : "=r"(v) : "r"(a)); return v;
}
__device__ __forceinline__ void mma8(float* c, const uint32_t* a, uint32_t b0, uint32_t b1){
    asm volatile("mma.sync.aligned.m16n8k8.row.col.f32.tf32.tf32.f32 "
        "{%0,%1,%2,%3}, {%4,%5,%6,%7}, {%8,%9}, {%0,%1,%2,%3};"
        : "+f"(c[0]), "+f"(c[1]), "+f"(c[2]), "+f"(c[3])
        : "r"(a[0]), "r"(a[1]), "r"(a[2]), "r"(a[3]), "r"(b0), "r"(b1));
}

// ---------------- prep: index dtype detect (parallel) ------------------------
__global__ void prep_idx_detect(const int* w){
    // int64 data => every high word is 0 or -1. Scan first n/2 pairs only so
    // we never read past an int32-sized buffer. g_i64 statically 1; we only
    // ever write 0 => deterministic across graph replays for fixed input.
    const int half = (KK * LL) / 2;
    int i = blockIdx.x * blockDim.x + threadIdx.x;
    int stride = gridDim.x * blockDim.x;
    for (; i < half; i += stride){
        int hi = w[2 * i + 1];
        if (hi != 0 && hi != -1) g_i64 = 0;   // benign race, same value
    }
}

// ---------------- prep: x transpose (n,c,l) -> (n,l,c), tf32 round, float4 ---
// Block (8,32): 32c x 32l tile. Conflict-free smem, 128B-coalesced both ways.
__global__ void prep_xT(const float* __restrict__ x){
    __shared__ float tile[32][33];
    int n = blockIdx.z;
    int c0 = blockIdx.y * 32, l0 = blockIdx.x * 32;
    int tx = threadIdx.x;      // 0..7 : float4 along l
    int ty = threadIdx.y;      // 0..31: c (load) / l (store)

    const float4 v = *(const float4*)(x + ((size_t)n * CIN + c0 + ty) * LL + l0 + tx * 4);
    tile[ty][tx * 4 + 0] = v.x;
    tile[ty][tx * 4 + 1] = v.y;
    tile[ty][tx * 4 + 2] = v.z;
    tile[ty][tx * 4 + 3] = v.w;
    __syncthreads();

    float4 o;
    o.x = to_tf32(tile[tx * 4 + 0][ty]);
    o.y = to_tf32(tile[tx * 4 + 1][ty]);
    o.z = to_tf32(tile[tx * 4 + 2][ty]);
    o.w = to_tf32(tile[tx * 4 + 3][ty]);
    *(float4*)(g_xT + ((size_t)n * LL + l0 + ty) * CIN + c0 + tx * 4) = o;
}

// ---------------- prep: weight repack (o,c,k) -> B[o][k*128+c], tf32 round ---
__global__ void prep_w(const float* __restrict__ w){
    int t = blockIdx.x * blockDim.x + threadIdx.x;
    if (t >= COUT * KC) return;
    int o = t / KC, r = t % KC;
    int k = r >> 7, c = r & 127;
    g_Bm[t] = to_tf32(w[(size_t)(o * CIN + c) * KK + k]);
}

// ---------------- SMEM layout (bytes) ----------------------------------------
// A: 2 stages x [128 rows][128B]; B: same; soff: 7*128 ints; sbias: 128 f.
#define SM_A     0
#define SM_B     32768
#define SM_OFF   65536
#define SM_BIAS  (65536 + 3584)
#define SMEM_TOTAL (SM_BIAS + 512)   // 69632; x3 CTAs = 208896 <= 228KB/SM

// ---------------- main: gather-GEMM, 4 warps x (64x64), 2-stage, 3 CTA/SM ----
__global__ void __launch_bounds__(THREADS, 3) conv_main(
    const void* __restrict__ idx_raw,
    const float* __restrict__ bias, float* __restrict__ out)
{
    extern __shared__ char smem[];
    uint32_t sb = smem_u32(smem);
    int tid = threadIdx.x;
    int l0 = blockIdx.x * BM;
    int n  = blockIdx.y;
    int nbase = blockIdx.z * BN;

    int* soff = (int*)(smem + SM_OFF);
    float* sbias = (float*)(smem + SM_BIAS);
    if (g_i64){
        const long long* q = (const long long*)idx_raw;
        for (int t = tid; t < KK * BM; t += THREADS){
            int k = t >> 7, r = t & 127;
            long long v = q[k * LL + l0 + r];
            soff[t] = (v >= 0) ? (int)v : -1;
        }
    } else {
        const int* q = (const int*)idx_raw;
        for (int t = tid; t < KK * BM; t += THREADS){
            int k = t >> 7, r = t & 127;
            int v = q[k * LL + l0 + r];
            soff[t] = (v >= 0) ? v : -1;
        }
    }
    if (tid < BN) sbias[tid] = bias[nbase + tid];
    __syncthreads();

    const float* xn = g_xT + (size_t)n * LL * CIN;
    const int s  = tid & 7;    // 16B chunk within 128B row
    const int rb = tid >> 3;   // 0..15

    // ---- tile loader (A gathered + masked, B dense); one commit group ----
    auto load_tile = [&](int i){
        int stage = i & 1;
        int k = i >> 2;
        int c0 = (i & 3) * 32;
        uint32_t abase = sb + SM_A + stage * 16384;
        uint32_t bbase = sb + SM_B + stage * 16384;
        #pragma unroll
        for (int p = 0; p < 8; p++){
            int r = p * 16 + rb;
            int off = soff[(k << 7) + r];
            const float* asrc = xn + (size_t)(off < 0 ? 0 : off) * CIN + c0 + s * 4;
            uint32_t sw = (uint32_t)((s ^ (r & 7)) * 16);
            cpa16(abase + r * 128 + sw, asrc, off >= 0 ? 16 : 0);
            const float* bsrc = g_Bm + (size_t)(nbase + r) * KC + i * 32 + s * 4;
            cpa16(bbase + r * 128 + sw, bsrc, 16);
        }
        asm volatile("cp.async.commit_group;" ::: "memory");
    };

    const int wid = tid >> 5, lane = tid & 31;
    const int wm = wid & 1;          // 2 warps along M (64 rows each)
    const int wn = wid >> 1;         // 2 warps along N (64 cols each)
    const int g = lane >> 2, t4 = lane & 3;

    float acc[4][8][4];
    #pragma unroll
    for (int a = 0; a < 4; a++)
        #pragma unroll
        for (int b = 0; b < 8; b++)
            #pragma unroll
            for (int c = 0; c < 4; c++) acc[a][b][c] = 0.f;

    load_tile(0);

    for (int i = 0; i < NITER; i++){
        // load(i+1) writes stage (i+1)&1 = (i-1)&1, whose readers (compute(i-1))
        // were fenced by the trailing __syncthreads of iteration i-1. Safe.
        if (i + 1 < NITER){
            load_tile(i + 1);
            asm volatile("cp.async.wait_group 1;" ::: "memory");
        } else {
            asm volatile("cp.async.wait_group 0;" ::: "memory");
        }
        __syncthreads();   // all warps' group-i data landed & visible

        int stage = i & 1;
        uint32_t ab = sb + SM_A + stage * 16384;
        uint32_t bb = sb + SM_B + stage * 16384;
        #pragma unroll
        for (int ks = 0; ks < 4; ks++){
            uint32_t ch0 = (uint32_t)(((2 * ks)     ^ g) * 16);
            uint32_t ch1 = (uint32_t)(((2 * ks + 1) ^ g) * 16);
            uint32_t afrag[4][4];
            #pragma unroll
            for (int mt = 0; mt < 4; mt++){
                int r = wm * 64 + mt * 16 + g;          // r&7 == g
                afrag[mt][0] = lds32(ab + r * 128       + ch0 + t4 * 4);
                afrag[mt][1] = lds32(ab + (r + 8) * 128 + ch0 + t4 * 4);
                afrag[mt][2] = lds32(ab + r * 128       + ch1 + t4 * 4);
                afrag[mt][3] = lds32(ab + (r + 8) * 128 + ch1 + t4 * 4);
            }
            #pragma unroll
            for (int nt = 0; nt < 8; nt++){
                int nr = wn * 64 + nt * 8 + g;          // nr&7 == g
                uint32_t b0 = lds32(bb + nr * 128 + ch0 + t4 * 4);
                uint32_t b1 = lds32(bb + nr * 128 + ch1 + t4 * 4);
                #pragma unroll
                for (int mt = 0; mt < 4; mt++)
                    mma8(acc[mt][nt], afrag[mt], b0, b1);
            }
        }
        __syncthreads();   // compute(i) done before load(i+2) overwrites stage i
    }

    // ---- epilogue: direct stores + bias ----
    float* outn = out + (size_t)n * COUT * LL;
    #pragma unroll
    for (int mt = 0; mt < 4; mt++){
        int l = l0 + wm * 64 + mt * 16 + g;
        #pragma unroll
        for (int nt = 0; nt < 8; nt++){
            int ol = wn * 64 + nt * 8 + 2 * t4;
            int o  = nbase + ol;
            float bv0 = sbias[ol], bv1 = sbias[ol + 1];
            outn[(size_t)o * LL + l]           = acc[mt][nt][0] + bv0;
            outn[(size_t)(o + 1) * LL + l]     = acc[mt][nt][1] + bv1;
            outn[(size_t)o * LL + l + 8]       = acc[mt][nt][2] + bv0;
            outn[(size_t)(o + 1) * LL + l + 8] = acc[mt][nt][3] + bv1;
        }
    }
}

// ---------------- launch ------------------------------------------------------
extern "C" void kernel_launch(void* const* d_in, const int* in_sizes, int n_in,
                              void* d_out, int out_size){
    const float* x    = (const float*)d_in[0];
    const void*  idx  = d_in[1];
    const float* w    = (const float*)d_in[2];
    const float* bias = (const float*)d_in[3];
    float* out = (float*)d_out;
    (void)in_sizes; (void)n_in; (void)out_size;

    cudaFuncSetAttribute(conv_main, cudaFuncAttributeMaxDynamicSharedMemorySize, SMEM_TOTAL);

    prep_idx_detect<<<148, 256>>>((const int*)idx);
    prep_xT<<<dim3(LL / 32, CIN / 32, NB), dim3(8, 32)>>>(x);
    prep_w<<<(COUT * KC + 255) / 256, 256>>>(w);
    conv_main<<<dim3(LL / BM, NB, COUT / BN), THREADS, SMEM_TOTAL>>>(idx, bias, out);
}

// round 12
// speedup vs baseline: 1.2236x; 1.2236x over previous
#include <cuda_runtime.h>
#include <cstdint>

#define NB   8
#define CIN  128
#define COUT 256
#define KK   7
#define LL   16384
#define KC   896        // KK*CIN

#define BM 128
#define BN 128
#define BK 32
#define NITER 28        // KC/BK
#define THREADS 128
#define NSTAGE 3

// ---------------- device scratch (allocation-free rule: __device__ globals) ---
__device__ float g_xT[(size_t)NB * LL * CIN];   // x transposed to (n,l,c), tf32-rounded
__device__ float g_Bm[(size_t)COUT * KC];       // B[o][k*128+c], tf32-rounded
__device__ int   g_i64 = 1;                     // 1 if idx buffer is int64 (detect only clears)

// ---------------- helpers ----------------------------------------------------
__device__ __forceinline__ uint32_t smem_u32(const void* p){
    uint32_t a;
    asm("{ .reg .u64 t; cvta.to.shared.u64 t, %1; cvt.u32.u64 %0, t; }" : "=r"(a) : "l"(p));
    return a;
}
__device__ __forceinline__ float to_tf32(float f){
    uint32_t u; asm("cvt.rna.tf32.f32 %0, %1;" : "=r"(u) : "f"(f));
    return __uint_as_float(u);
}
__device__ __forceinline__ void cpa16(uint32_t dst, const void* src, int pbytes){
    asm volatile("cp.async.cg.shared.global [%0], [%1], 16, %2;"
        :: "r"(dst), "l"(src), "r"(pbytes) : "memory");
}
__device__ __forceinline__ uint32_t lds32(uint32_t a){
    uint32_t v; asm volatile("ld.shared.b32 %0, [%1];" : "=r"(v) : "r"(a)); return v;
}
__device__ __forceinline__ void mma8(float* c, const uint32_t* a, uint32_t b0, uint32_t b1){
    asm volatile("mma.sync.aligned.m16n8k8.row.col.f32.tf32.tf32.f32 "
        "{%0,%1,%2,%3}, {%4,%5,%6,%7}, {%8,%9}, {%0,%1,%2,%3};"
        : "+f"(c[0]), "+f"(c[1]), "+f"(c[2]), "+f"(c[3])
        : "r"(a[0]), "r"(a[1]), "r"(a[2]), "r"(a[3]), "r"(b0), "r"(b1));
}

// ---------------- prep: index dtype detect (parallel) ------------------------
__global__ void prep_idx_detect(const int* w){
    // int64 data => every high word is 0 or -1. Scan first n/2 pairs only so
    // we never read past an int32-sized buffer. g_i64 statically 1; we only
    // ever write 0 => deterministic across graph replays for fixed input.
    const int half = (KK * LL) / 2;
    int i = blockIdx.x * blockDim.x + threadIdx.x;
    int stride = gridDim.x * blockDim.x;
    for (; i < half; i += stride){
        int hi = w[2 * i + 1];
        if (hi != 0 && hi != -1) g_i64 = 0;   // benign race, same value
    }
}

// ---------------- prep: x transpose (n,c,l) -> (n,l,c), tf32 round, float4 ---
// Block (8,32): 32c x 32l tile. Conflict-free smem, 128B-coalesced both ways.
__global__ void prep_xT(const float* __restrict__ x){
    __shared__ float tile[32][33];
    int n = blockIdx.z;
    int c0 = blockIdx.y * 32, l0 = blockIdx.x * 32;
    int tx = threadIdx.x;      // 0..7 : float4 along l
    int ty = threadIdx.y;      // 0..31: c (load) / l (store)

    const float4 v = *(const float4*)(x + ((size_t)n * CIN + c0 + ty) * LL + l0 + tx * 4);
    tile[ty][tx * 4 + 0] = v.x;
    tile[ty][tx * 4 + 1] = v.y;
    tile[ty][tx * 4 + 2] = v.z;
    tile[ty][tx * 4 + 3] = v.w;
    __syncthreads();

    float4 o;
    o.x = to_tf32(tile[tx * 4 + 0][ty]);
    o.y = to_tf32(tile[tx * 4 + 1][ty]);
    o.z = to_tf32(tile[tx * 4 + 2][ty]);
    o.w = to_tf32(tile[tx * 4 + 3][ty]);
    *(float4*)(g_xT + ((size_t)n * LL + l0 + ty) * CIN + c0 + tx * 4) = o;
}

// ---------------- prep: weight repack (o,c,k) -> B[o][k*128+c], tf32 round ---
__global__ void prep_w(const float* __restrict__ w){
    int t = blockIdx.x * blockDim.x + threadIdx.x;
    if (t >= COUT * KC) return;
    int o = t / KC, r = t % KC;
    int k = r >> 7, c = r & 127;
    g_Bm[t] = to_tf32(w[(size_t)(o * CIN + c) * KK + k]);
}

// ---------------- SMEM layout (bytes) ----------------------------------------
// A: 3 stages x [128 rows][128B]; B: same; soff: 7*128 ints; sbias: 128 f.
#define SM_A     0
#define SM_B     49152
#define SM_OFF   98304
#define SM_BIAS  (98304 + 3584)
#define SMEM_TOTAL (SM_BIAS + 512)   // 102400; x2 CTAs = 200KB < 228KB/SM

// ---------------- main: gather-GEMM, 4 warps x (64x64), 3-stage, A-hoisted ---
__global__ void __launch_bounds__(THREADS, 2) conv_main(
    const void* __restrict__ idx_raw,
    const float* __restrict__ bias, float* __restrict__ out)
{
    extern __shared__ char smem[];
    uint32_t sb = smem_u32(smem);
    int tid = threadIdx.x;
    int l0 = blockIdx.x * BM;
    int n  = blockIdx.y;
    int nbase = blockIdx.z * BN;

    int* soff = (int*)(smem + SM_OFF);
    float* sbias = (float*)(smem + SM_BIAS);
    if (g_i64){
        const long long* q = (const long long*)idx_raw;
        for (int t = tid; t < KK * BM; t += THREADS){
            int k = t >> 7, r = t & 127;
            long long v = q[k * LL + l0 + r];
            soff[t] = (v >= 0) ? (int)v : -1;
        }
    } else {
        const int* q = (const int*)idx_raw;
        for (int t = tid; t < KK * BM; t += THREADS){
            int k = t >> 7, r = t & 127;
            int v = q[k * LL + l0 + r];
            soff[t] = (v >= 0) ? v : -1;
        }
    }
    if (tid < BN) sbias[tid] = bias[nbase + tid];
    __syncthreads();

    const float* xn = g_xT + (size_t)n * LL * CIN;
    const int s  = tid & 7;    // 16B chunk within 128B row
    const int rb = tid >> 3;   // 0..15

    // ---- tile loader (A gathered + masked, B dense); one commit group ----
    auto load_tile = [&](int i){
        int stage = i % NSTAGE;
        int k = i >> 2;
        int c0 = (i & 3) * 32;
        uint32_t abase = sb + SM_A + stage * 16384;
        uint32_t bbase = sb + SM_B + stage * 16384;
        #pragma unroll
        for (int p = 0; p < 8; p++){
            int r = p * 16 + rb;
            int off = soff[(k << 7) + r];
            const float* asrc = xn + (size_t)(off < 0 ? 0 : off) * CIN + c0 + s * 4;
            uint32_t sw = (uint32_t)((s ^ (r & 7)) * 16);
            cpa16(abase + r * 128 + sw, asrc, off >= 0 ? 16 : 0);
            const float* bsrc = g_Bm + (size_t)(nbase + r) * KC + i * 32 + s * 4;
            cpa16(bbase + r * 128 + sw, bsrc, 16);
        }
        asm volatile("cp.async.commit_group;" ::: "memory");
    };

    const int wid = tid >> 5, lane = tid & 31;
    const int wm = wid & 1;          // 2 warps along M (64 rows each)
    const int wn = wid >> 1;         // 2 warps along N (64 cols each)
    const int g = lane >> 2, t4 = lane & 3;

    float acc[4][8][4];
    #pragma unroll
    for (int a = 0; a < 4; a++)
        #pragma unroll
        for (int b = 0; b < 8; b++)
            #pragma unroll
            for (int c = 0; c < 4; c++) acc[a][b][c] = 0.f;

    load_tile(0);
    load_tile(1);

    for (int i = 0; i < NITER; i++){
        if (i >= NITER - 1)
            asm volatile("cp.async.wait_group 0;" ::: "memory");
        else
            asm volatile("cp.async.wait_group 1;" ::: "memory");
        __syncthreads();
        if (i + 2 < NITER) load_tile(i + 2);

        int stage = i % NSTAGE;
        uint32_t ab = sb + SM_A + stage * 16384;
        uint32_t bb = sb + SM_B + stage * 16384;

        // ---- hoist ALL A fragments for this iteration (64 regs) ----
        uint32_t afrag[4][4][4];   // [ks][mt][e]
        #pragma unroll
        for (int ks = 0; ks < 4; ks++){
            uint32_t ch0 = (uint32_t)(((2 * ks)     ^ g) * 16);
            uint32_t ch1 = (uint32_t)(((2 * ks + 1) ^ g) * 16);
            #pragma unroll
            for (int mt = 0; mt < 4; mt++){
                int r = wm * 64 + mt * 16 + g;          // r&7 == g
                afrag[ks][mt][0] = lds32(ab + r * 128       + ch0 + t4 * 4);
                afrag[ks][mt][1] = lds32(ab + (r + 8) * 128 + ch0 + t4 * 4);
                afrag[ks][mt][2] = lds32(ab + r * 128       + ch1 + t4 * 4);
                afrag[ks][mt][3] = lds32(ab + (r + 8) * 128 + ch1 + t4 * 4);
            }
        }

        // ---- stream B, feed mma (A already resident) ----
        #pragma unroll
        for (int ks = 0; ks < 4; ks++){
            uint32_t ch0 = (uint32_t)(((2 * ks)     ^ g) * 16);
            uint32_t ch1 = (uint32_t)(((2 * ks + 1) ^ g) * 16);
            #pragma unroll
            for (int nt = 0; nt < 8; nt++){
                int nr = wn * 64 + nt * 8 + g;          // nr&7 == g
                uint32_t b0 = lds32(bb + nr * 128 + ch0 + t4 * 4);
                uint32_t b1 = lds32(bb + nr * 128 + ch1 + t4 * 4);
                #pragma unroll
                for (int mt = 0; mt < 4; mt++)
                    mma8(acc[mt][nt], afrag[ks][mt], b0, b1);
            }
        }
    }

    // ---- epilogue: direct stores + bias ----
    float* outn = out + (size_t)n * COUT * LL;
    #pragma unroll
    for (int mt = 0; mt < 4; mt++){
        int l = l0 + wm * 64 + mt * 16 + g;
        #pragma unroll
        for (int nt = 0; nt < 8; nt++){
            int ol = wn * 64 + nt * 8 + 2 * t4;
            int o  = nbase + ol;
            float bv0 = sbias[ol], bv1 = sbias[ol + 1];
            outn[(size_t)o * LL + l]           = acc[mt][nt][0] + bv0;
            outn[(size_t)(o + 1) * LL + l]     = acc[mt][nt][1] + bv1;
            outn[(size_t)o * LL + l + 8]       = acc[mt][nt][2] + bv0;
            outn[(size_t)(o + 1) * LL + l + 8] = acc[mt][nt][3] + bv1;
        }
    }
}

// ---------------- launch ------------------------------------------------------
extern "C" void kernel_launch(void* const* d_in, const int* in_sizes, int n_in,
                              void* d_out, int out_size){
    const float* x    = (const float*)d_in[0];
    const void*  idx  = d_in[1];
    const float* w    = (const float*)d_in[2];
    const float* bias = (const float*)d_in[3];
    float* out = (float*)d_out;
    (void)in_sizes; (void)n_in; (void)out_size;

    cudaFuncSetAttribute(conv_main, cudaFuncAttributeMaxDynamicSharedMemorySize, SMEM_TOTAL);

    prep_idx_detect<<<148, 256>>>((const int*)idx);
    prep_xT<<<dim3(LL / 32, CIN / 32, NB), dim3(8, 32)>>>(x);
    prep_w<<<(COUT * KC + 255) / 256, 256>>>(w);
    conv_main<<<dim3(LL / BM, NB, COUT / BN), THREADS, SMEM_TOTAL>>>(idx, bias, out);
}

// round 13
// speedup vs baseline: 1.3340x; 1.0903x over previous
#include <cuda_runtime.h>
#include <cstdint>

#define NB   8
#define CIN  128
#define COUT 256
#define KK   7
#define LL   16384
#define KC   896        // KK*CIN

#define BM 128
#define BN 128
#define BK 32
#define NITER 28        // KC/BK
#define THREADS 128
#define NSTAGE 3

// ---------------- device scratch (allocation-free rule: __device__ globals) ---
__device__ float g_xT[(size_t)NB * LL * CIN];   // x transposed to (n,l,c), tf32-rounded
__device__ float g_Bm[(size_t)COUT * KC];       // B[o][k*128+c], tf32-rounded
__device__ int   g_i64 = 1;                     // 1 if idx buffer is int64 (detect only clears)

// ---------------- helpers ----------------------------------------------------
__device__ __forceinline__ uint32_t smem_u32(const void* p){
    uint32_t a;
    asm("{ .reg .u64 t; cvta.to.shared.u64 t, %1; cvt.u32.u64 %0, t; }" : "=r"(a) : "l"(p));
    return a;
}
__device__ __forceinline__ float to_tf32(float f){
    uint32_t u; asm("cvt.rna.tf32.f32 %0, %1;" : "=r"(u) : "f"(f));
    return __uint_as_float(u);
}
__device__ __forceinline__ void cpa16(uint32_t dst, const void* src, int pbytes){
    asm volatile("cp.async.cg.shared.global [%0], [%1], 16, %2;"
        :: "r"(dst), "l"(src), "r"(pbytes) : "memory");
}
__device__ __forceinline__ void ldsm4(uint32_t* r, uint32_t a){
    asm volatile("ldmatrix.sync.aligned.m8n8.x4.shared.b16 {%0,%1,%2,%3}, [%4];"
        : "=r"(r[0]), "=r"(r[1]), "=r"(r[2]), "=r"(r[3]) : "r"(a));
}
__device__ __forceinline__ void ldsm2(uint32_t& b0, uint32_t& b1, uint32_t a){
    asm volatile("ldmatrix.sync.aligned.m8n8.x2.shared.b16 {%0,%1}, [%2];"
        : "=r"(b0), "=r"(b1) : "r"(a));
}
__device__ __forceinline__ void mma8(float* c, const uint32_t* a, uint32_t b0, uint32_t b1){
    asm volatile("mma.sync.aligned.m16n8k8.row.col.f32.tf32.tf32.f32 "
        "{%0,%1,%2,%3}, {%4,%5,%6,%7}, {%8,%9}, {%0,%1,%2,%3};"
        : "+f"(c[0]), "+f"(c[1]), "+f"(c[2]), "+f"(c[3])
        : "r"(a[0]), "r"(a[1]), "r"(a[2]), "r"(a[3]), "r"(b0), "r"(b1));
}

// ---------------- prep: index dtype detect (parallel) ------------------------
__global__ void prep_idx_detect(const int* w){
    // int64 data => every high word is 0 or -1. Scan first n/2 pairs only so
    // we never read past an int32-sized buffer. g_i64 statically 1; we only
    // ever write 0 => deterministic across graph replays for fixed input.
    const int half = (KK * LL) / 2;
    int i = blockIdx.x * blockDim.x + threadIdx.x;
    int stride = gridDim.x * blockDim.x;
    for (; i < half; i += stride){
        int hi = w[2 * i + 1];
        if (hi != 0 && hi != -1) g_i64 = 0;   // benign race, same value
    }
}

// ---------------- prep: x transpose (n,c,l) -> (n,l,c), tf32 round, float4 ---
// Block (8,32): 32c x 32l tile. Conflict-free smem, 128B-coalesced both ways.
__global__ void prep_xT(const float* __restrict__ x){
    __shared__ float tile[32][33];
    int n = blockIdx.z;
    int c0 = blockIdx.y * 32, l0 = blockIdx.x * 32;
    int tx = threadIdx.x;      // 0..7 : float4 along l
    int ty = threadIdx.y;      // 0..31: c (load) / l (store)

    const float4 v = *(const float4*)(x + ((size_t)n * CIN + c0 + ty) * LL + l0 + tx * 4);
    tile[ty][tx * 4 + 0] = v.x;
    tile[ty][tx * 4 + 1] = v.y;
    tile[ty][tx * 4 + 2] = v.z;
    tile[ty][tx * 4 + 3] = v.w;
    __syncthreads();

    float4 o;
    o.x = to_tf32(tile[tx * 4 + 0][ty]);
    o.y = to_tf32(tile[tx * 4 + 1][ty]);
    o.z = to_tf32(tile[tx * 4 + 2][ty]);
    o.w = to_tf32(tile[tx * 4 + 3][ty]);
    *(float4*)(g_xT + ((size_t)n * LL + l0 + ty) * CIN + c0 + tx * 4) = o;
}

// ---------------- prep: weight repack (o,c,k) -> B[o][k*128+c], tf32 round ---
__global__ void prep_w(const float* __restrict__ w){
    int t = blockIdx.x * blockDim.x + threadIdx.x;
    if (t >= COUT * KC) return;
    int o = t / KC, r = t % KC;
    int k = r >> 7, c = r & 127;
    g_Bm[t] = to_tf32(w[(size_t)(o * CIN + c) * KK + k]);
}

// ---------------- SMEM layout (bytes) ----------------------------------------
// A: 3 stages x [128 rows][128B]; B: same; soff: 7*128 ints; sbias: 128 f.
#define SM_A     0
#define SM_B     49152
#define SM_OFF   98304
#define SM_BIAS  (98304 + 3584)
#define SMEM_TOTAL (SM_BIAS + 512)   // 102400; x2 CTAs = 200KB < 228KB/SM

// ---------------- main: gather-GEMM, ldmatrix fragments, 3-stage -------------
__global__ void __launch_bounds__(THREADS, 2) conv_main(
    const void* __restrict__ idx_raw,
    const float* __restrict__ bias, float* __restrict__ out)
{
    extern __shared__ char smem[];
    uint32_t sb = smem_u32(smem);
    int tid = threadIdx.x;
    int l0 = blockIdx.x * BM;
    int n  = blockIdx.y;
    int nbase = blockIdx.z * BN;

    int* soff = (int*)(smem + SM_OFF);
    float* sbias = (float*)(smem + SM_BIAS);
    if (g_i64){
        const long long* q = (const long long*)idx_raw;
        for (int t = tid; t < KK * BM; t += THREADS){
            int k = t >> 7, r = t & 127;
            long long v = q[k * LL + l0 + r];
            soff[t] = (v >= 0) ? (int)v : -1;
        }
    } else {
        const int* q = (const int*)idx_raw;
        for (int t = tid; t < KK * BM; t += THREADS){
            int k = t >> 7, r = t & 127;
            int v = q[k * LL + l0 + r];
            soff[t] = (v >= 0) ? v : -1;
        }
    }
    if (tid < BN) sbias[tid] = bias[nbase + tid];
    __syncthreads();

    const float* xn = g_xT + (size_t)n * LL * CIN;
    const int s  = tid & 7;    // 16B chunk within 128B row
    const int rb = tid >> 3;   // 0..15

    // ---- tile loader (A gathered + masked, B dense); one commit group ----
    auto load_tile = [&](int i){
        int stage = i % NSTAGE;
        int k = i >> 2;
        int c0 = (i & 3) * 32;
        uint32_t abase = sb + SM_A + stage * 16384;
        uint32_t bbase = sb + SM_B + stage * 16384;
        #pragma unroll
        for (int p = 0; p < 8; p++){
            int r = p * 16 + rb;
            int off = soff[(k << 7) + r];
            const float* asrc = xn + (size_t)(off < 0 ? 0 : off) * CIN + c0 + s * 4;
            uint32_t sw = (uint32_t)((s ^ (r & 7)) * 16);
            cpa16(abase + r * 128 + sw, asrc, off >= 0 ? 16 : 0);
            const float* bsrc = g_Bm + (size_t)(nbase + r) * KC + i * 32 + s * 4;
            cpa16(bbase + r * 128 + sw, bsrc, 16);
        }
        asm volatile("cp.async.commit_group;" ::: "memory");
    };

    const int wid = tid >> 5, lane = tid & 31;
    const int wm = wid & 1;          // 2 warps along M (64 rows each)
    const int wn = wid >> 1;         // 2 warps along N (64 cols each)
    const int g = lane >> 2, t4 = lane & 3;

    // ---- ldmatrix per-lane address components (precomputed) ----
    // A x4: lane L -> tile L/8 in {r0..7/c0..3, r8..15/c0..3, r0..7/c4..7, r8..15/c4..7}
    const int aR  = lane & 7;              // row within 8-row tile
    const int aH8 = (lane >> 3) & 1;       // +8 rows (tiles 1,3)
    const int aCC = lane >> 4;             // +1 col-chunk (tiles 2,3)
    uint32_t rowA[4];                      // byte offset of this lane's A row per mt
    #pragma unroll
    for (int mt = 0; mt < 4; mt++)
        rowA[mt] = (uint32_t)((wm * 64 + mt * 16 + aR + aH8 * 8) * 128);
    uint32_t swzA[4];                      // swizzled col-chunk byte per ks
    #pragma unroll
    for (int ks = 0; ks < 4; ks++)
        swzA[ks] = (uint32_t)(((2 * ks + aCC) ^ aR) * 16);

    // B x2: lanes 0-15 provide addresses; tile L/8 in {c0..3, c4..7}
    const int bR  = lane & 7;
    const int bH  = (lane >> 3) & 1;
    const uint32_t rowB0 = (uint32_t)((wn * 64 + bR) * 128);
    uint32_t swzB[4];
    #pragma unroll
    for (int ks = 0; ks < 4; ks++)
        swzB[ks] = (uint32_t)(((2 * ks + bH) ^ bR) * 16);

    float acc[4][8][4];
    #pragma unroll
    for (int a = 0; a < 4; a++)
        #pragma unroll
        for (int b = 0; b < 8; b++)
            #pragma unroll
            for (int c = 0; c < 4; c++) acc[a][b][c] = 0.f;

    load_tile(0);
    load_tile(1);

    for (int i = 0; i < NITER; i++){
        if (i >= NITER - 1)
            asm volatile("cp.async.wait_group 0;" ::: "memory");
        else
            asm volatile("cp.async.wait_group 1;" ::: "memory");
        __syncthreads();
        if (i + 2 < NITER) load_tile(i + 2);

        int stage = i % NSTAGE;
        uint32_t ab = sb + SM_A + stage * 16384;
        uint32_t bb = sb + SM_B + stage * 16384 + rowB0;

        // ---- hoist ALL A fragments: 16 ldmatrix.x4 ----
        uint32_t afrag[4][4][4];   // [ks][mt][e]
        #pragma unroll
        for (int ks = 0; ks < 4; ks++)
            #pragma unroll
            for (int mt = 0; mt < 4; mt++)
                ldsm4(afrag[ks][mt], ab + rowA[mt] + swzA[ks]);

        // ---- stream B via ldmatrix.x2, feed mma ----
        #pragma unroll
        for (int ks = 0; ks < 4; ks++){
            #pragma unroll
            for (int nt = 0; nt < 8; nt++){
                uint32_t b0, b1;
                ldsm2(b0, b1, bb + (uint32_t)(nt * 1024) + swzB[ks]);
                #pragma unroll
                for (int mt = 0; mt < 4; mt++)
                    mma8(acc[mt][nt], afrag[ks][mt], b0, b1);
            }
        }
    }

    // ---- epilogue: direct stores + bias ----
    float* outn = out + (size_t)n * COUT * LL;
    #pragma unroll
    for (int mt = 0; mt < 4; mt++){
        int l = l0 + wm * 64 + mt * 16 + g;
        #pragma unroll
        for (int nt = 0; nt < 8; nt++){
            int ol = wn * 64 + nt * 8 + 2 * t4;
            int o  = nbase + ol;
            float bv0 = sbias[ol], bv1 = sbias[ol + 1];
            outn[(size_t)o * LL + l]           = acc[mt][nt][0] + bv0;
            outn[(size_t)(o + 1) * LL + l]     = acc[mt][nt][1] + bv1;
            outn[(size_t)o * LL + l + 8]       = acc[mt][nt][2] + bv0;
            outn[(size_t)(o + 1) * LL + l + 8] = acc[mt][nt][3] + bv1;
        }
    }
}

// ---------------- launch ------------------------------------------------------
extern "C" void kernel_launch(void* const* d_in, const int* in_sizes, int n_in,
                              void* d_out, int out_size){
    const float* x    = (const float*)d_in[0];
    const void*  idx  = d_in[1];
    const float* w    = (const float*)d_in[2];
    const float* bias = (const float*)d_in[3];
    float* out = (float*)d_out;
    (void)in_sizes; (void)n_in; (void)out_size;

    cudaFuncSetAttribute(conv_main, cudaFuncAttributeMaxDynamicSharedMemorySize, SMEM_TOTAL);

    prep_idx_detect<<<148, 256>>>((const int*)idx);
    prep_xT<<<dim3(LL / 32, CIN / 32, NB), dim3(8, 32)>>>(x);
    prep_w<<<(COUT * KC + 255) / 256, 256>>>(w);
    conv_main<<<dim3(LL / BM, NB, COUT / BN), THREADS, SMEM_TOTAL>>>(idx, bias, out);
}

// round 14
// speedup vs baseline: 1.3489x; 1.0111x over previous
#include <cuda_runtime.h>
#include <cstdint>

#define NB   8
#define CIN  128
#define COUT 256
#define KK   7
#define LL   16384
#define KC   896        // KK*CIN

#define BM 128
#define BN 128
#define BK 32
#define NITER 28        // KC/BK
#define THREADS 128
#define NSTAGE 3

// ---------------- device scratch (allocation-free rule: __device__ globals) ---
__device__ float g_xT[(size_t)NB * LL * CIN];   // x transposed to (n,l,c), tf32-rounded
__device__ float g_Bm[(size_t)COUT * KC];       // B[o][k*128+c], tf32-rounded
__device__ int   g_i64 = 1;                     // 1 if idx buffer is int64 (detect only clears)

// ---------------- helpers ----------------------------------------------------
__device__ __forceinline__ uint32_t smem_u32(const void* p){
    uint32_t a;
    asm("{ .reg .u64 t; cvta.to.shared.u64 t, %1; cvt.u32.u64 %0, t; }" : "=r"(a) : "l"(p));
    return a;
}
__device__ __forceinline__ float to_tf32(float f){
    uint32_t u; asm("cvt.rna.tf32.f32 %0, %1;" : "=r"(u) : "f"(f));
    return __uint_as_float(u);
}
__device__ __forceinline__ void cpa16(uint32_t dst, const void* src, int pbytes){
    asm volatile("cp.async.cg.shared.global [%0], [%1], 16, %2;"
        :: "r"(dst), "l"(src), "r"(pbytes) : "memory");
}
__device__ __forceinline__ void ldsm4(uint32_t* r, uint32_t a){
    asm volatile("ldmatrix.sync.aligned.m8n8.x4.shared.b16 {%0,%1,%2,%3}, [%4];"
        : "=r"(r[0]), "=r"(r[1]), "=r"(r[2]), "=r"(r[3]) : "r"(a));
}
__device__ __forceinline__ void ldsm2(uint32_t& b0, uint32_t& b1, uint32_t a){
    asm volatile("ldmatrix.sync.aligned.m8n8.x2.shared.b16 {%0,%1}, [%2];"
        : "=r"(b0), "=r"(b1) : "r"(a));
}
__device__ __forceinline__ void mma8(float* c, const uint32_t* a, uint32_t b0, uint32_t b1){
    asm volatile("mma.sync.aligned.m16n8k8.row.col.f32.tf32.tf32.f32 "
        "{%0,%1,%2,%3}, {%4,%5,%6,%7}, {%8,%9}, {%0,%1,%2,%3};"
        : "+f"(c[0]), "+f"(c[1]), "+f"(c[2]), "+f"(c[3])
        : "r"(a[0]), "r"(a[1]), "r"(a[2]), "r"(a[3]), "r"(b0), "r"(b1));
}

// ---------------- prep: index dtype detect (parallel) ------------------------
__global__ void prep_idx_detect(const int* w){
    // int64 data => every high word is 0 or -1. Scan first n/2 pairs only so
    // we never read past an int32-sized buffer. g_i64 statically 1; we only
    // ever write 0 => deterministic across graph replays for fixed input.
    const int half = (KK * LL) / 2;
    int i = blockIdx.x * blockDim.x + threadIdx.x;
    int stride = gridDim.x * blockDim.x;
    for (; i < half; i += stride){
        int hi = w[2 * i + 1];
        if (hi != 0 && hi != -1) g_i64 = 0;   // benign race, same value
    }
}

// ---------------- prep: x transpose (n,c,l) -> (n,l,c), tf32 round, float4 ---
// Block (8,32): 32c x 32l tile. Conflict-free smem, 128B-coalesced both ways.
__global__ void prep_xT(const float* __restrict__ x){
    __shared__ float tile[32][33];
    int n = blockIdx.z;
    int c0 = blockIdx.y * 32, l0 = blockIdx.x * 32;
    int tx = threadIdx.x;      // 0..7 : float4 along l
    int ty = threadIdx.y;      // 0..31: c (load) / l (store)

    const float4 v = *(const float4*)(x + ((size_t)n * CIN + c0 + ty) * LL + l0 + tx * 4);
    tile[ty][tx * 4 + 0] = v.x;
    tile[ty][tx * 4 + 1] = v.y;
    tile[ty][tx * 4 + 2] = v.z;
    tile[ty][tx * 4 + 3] = v.w;
    __syncthreads();

    float4 o;
    o.x = to_tf32(tile[tx * 4 + 0][ty]);
    o.y = to_tf32(tile[tx * 4 + 1][ty]);
    o.z = to_tf32(tile[tx * 4 + 2][ty]);
    o.w = to_tf32(tile[tx * 4 + 3][ty]);
    *(float4*)(g_xT + ((size_t)n * LL + l0 + ty) * CIN + c0 + tx * 4) = o;
}

// ---------------- prep: weight repack (o,c,k) -> B[o][k*128+c], tf32 round ---
__global__ void prep_w(const float* __restrict__ w){
    int t = blockIdx.x * blockDim.x + threadIdx.x;
    if (t >= COUT * KC) return;
    int o = t / KC, r = t % KC;
    int k = r >> 7, c = r & 127;
    g_Bm[t] = to_tf32(w[(size_t)(o * CIN + c) * KK + k]);
}

// ---------------- SMEM layout (bytes) ----------------------------------------
// A: 3 stages x [128 rows][128B]; B: same; soff: 7*128 ints; sbias: 128 f.
#define SM_A     0
#define SM_B     49152
#define SM_OFF   98304
#define SM_BIAS  (98304 + 3584)
#define SMEM_TOTAL (SM_BIAS + 512)   // 102400; x2 CTAs = 200KB < 228KB/SM

// ---------------- main: gather-GEMM, ldmatrix + reg double-buffer, 3-stage ---
__global__ void __launch_bounds__(THREADS, 2) conv_main(
    const void* __restrict__ idx_raw,
    const float* __restrict__ bias, float* __restrict__ out)
{
    extern __shared__ char smem[];
    uint32_t sb = smem_u32(smem);
    int tid = threadIdx.x;
    int l0 = blockIdx.x * BM;
    int n  = blockIdx.y;
    int nbase = blockIdx.z * BN;

    int* soff = (int*)(smem + SM_OFF);
    float* sbias = (float*)(smem + SM_BIAS);
    if (g_i64){
        const long long* q = (const long long*)idx_raw;
        for (int t = tid; t < KK * BM; t += THREADS){
            int k = t >> 7, r = t & 127;
            long long v = q[k * LL + l0 + r];
            soff[t] = (v >= 0) ? (int)v : -1;
        }
    } else {
        const int* q = (const int*)idx_raw;
        for (int t = tid; t < KK * BM; t += THREADS){
            int k = t >> 7, r = t & 127;
            int v = q[k * LL + l0 + r];
            soff[t] = (v >= 0) ? v : -1;
        }
    }
    if (tid < BN) sbias[tid] = bias[nbase + tid];
    __syncthreads();

    const float* xn = g_xT + (size_t)n * LL * CIN;
    const int s  = tid & 7;    // 16B chunk within 128B row
    const int rb = tid >> 3;   // 0..15

    // ---- tile loader (A gathered + masked, B dense); one commit group ----
    auto load_tile = [&](int i){
        int stage = i % NSTAGE;
        int k = i >> 2;
        int c0 = (i & 3) * 32;
        uint32_t abase = sb + SM_A + stage * 16384;
        uint32_t bbase = sb + SM_B + stage * 16384;
        #pragma unroll
        for (int p = 0; p < 8; p++){
            int r = p * 16 + rb;
            int off = soff[(k << 7) + r];
            const float* asrc = xn + (size_t)(off < 0 ? 0 : off) * CIN + c0 + s * 4;
            uint32_t sw = (uint32_t)((s ^ (r & 7)) * 16);
            cpa16(abase + r * 128 + sw, asrc, off >= 0 ? 16 : 0);
            const float* bsrc = g_Bm + (size_t)(nbase + r) * KC + i * 32 + s * 4;
            cpa16(bbase + r * 128 + sw, bsrc, 16);
        }
        asm volatile("cp.async.commit_group;" ::: "memory");
    };

    const int wid = tid >> 5, lane = tid & 31;
    const int wm = wid & 1;          // 2 warps along M (64 rows each)
    const int wn = wid >> 1;         // 2 warps along N (64 cols each)
    const int g = lane >> 2, t4 = lane & 3;

    // ---- ldmatrix per-lane address components (precomputed) ----
    const int aR  = lane & 7;              // row within 8-row tile
    const int aH8 = (lane >> 3) & 1;       // +8 rows (tiles 1,3)
    const int aCC = lane >> 4;             // +1 col-chunk (tiles 2,3)
    uint32_t rowA[4];
    #pragma unroll
    for (int mt = 0; mt < 4; mt++)
        rowA[mt] = (uint32_t)((wm * 64 + mt * 16 + aR + aH8 * 8) * 128);
    uint32_t swzA[4];
    #pragma unroll
    for (int ks = 0; ks < 4; ks++)
        swzA[ks] = (uint32_t)(((2 * ks + aCC) ^ aR) * 16);

    const int bR  = lane & 7;
    const int bH  = (lane >> 3) & 1;
    const uint32_t rowB0 = (uint32_t)((wn * 64 + bR) * 128);
    uint32_t swzB[4];
    #pragma unroll
    for (int ks = 0; ks < 4; ks++)
        swzB[ks] = (uint32_t)(((2 * ks + bH) ^ bR) * 16);

    float acc[4][8][4];
    #pragma unroll
    for (int a = 0; a < 4; a++)
        #pragma unroll
        for (int b = 0; b < 8; b++)
            #pragma unroll
            for (int c = 0; c < 4; c++) acc[a][b][c] = 0.f;

    load_tile(0);
    load_tile(1);

    for (int i = 0; i < NITER; i++){
        if (i >= NITER - 1)
            asm volatile("cp.async.wait_group 0;" ::: "memory");
        else
            asm volatile("cp.async.wait_group 1;" ::: "memory");
        __syncthreads();
        if (i + 2 < NITER) load_tile(i + 2);

        int stage = i % NSTAGE;
        uint32_t ab = sb + SM_A + stage * 16384;
        uint32_t bb = sb + SM_B + stage * 16384 + rowB0;

        // ---- software-pipelined fragment stream ----
        // A: double-buffered across ks (prefetch ks+1 spread over nt=1..4)
        // B: double-buffered across nt (prefetch nt+1 before mma of nt)
        uint32_t afr[2][4][4];
        #pragma unroll
        for (int mt = 0; mt < 4; mt++)
            ldsm4(afr[0][mt], ab + rowA[mt] + swzA[0]);
        uint32_t b0c, b1c, b0n, b1n;
        ldsm2(b0c, b1c, bb + swzB[0]);                 // (ks=0, nt=0)

        #pragma unroll
        for (int ks = 0; ks < 4; ks++){
            const int cur = ks & 1;
            #pragma unroll
            for (int nt = 0; nt < 8; nt++){
                if (!(ks == 3 && nt == 7)){
                    const int nks = (nt == 7) ? ks + 1 : ks;
                    const int nnt = (nt == 7) ? 0 : nt + 1;
                    ldsm2(b0n, b1n, bb + (uint32_t)(nnt * 1024) + swzB[nks & 3]);
                }
                if (ks < 3 && nt >= 1 && nt <= 4)
                    ldsm4(afr[cur ^ 1][nt - 1], ab + rowA[nt - 1] + swzA[ks + 1]);
                #pragma unroll
                for (int mt = 0; mt < 4; mt++)
                    mma8(acc[mt][nt], afr[cur][mt], b0c, b1c);
                b0c = b0n; b1c = b1n;
            }
        }
    }

    // ---- epilogue: direct stores + bias ----
    float* outn = out + (size_t)n * COUT * LL;
    #pragma unroll
    for (int mt = 0; mt < 4; mt++){
        int l = l0 + wm * 64 + mt * 16 + g;
        #pragma unroll
        for (int nt = 0; nt < 8; nt++){
            int ol = wn * 64 + nt * 8 + 2 * t4;
            int o  = nbase + ol;
            float bv0 = sbias[ol], bv1 = sbias[ol + 1];
            outn[(size_t)o * LL + l]           = acc[mt][nt][0] + bv0;
            outn[(size_t)(o + 1) * LL + l]     = acc[mt][nt][1] + bv1;
            outn[(size_t)o * LL + l + 8]       = acc[mt][nt][2] + bv0;
            outn[(size_t)(o + 1) * LL + l + 8] = acc[mt][nt][3] + bv1;
        }
    }
}

// ---------------- launch ------------------------------------------------------
extern "C" void kernel_launch(void* const* d_in, const int* in_sizes, int n_in,
                              void* d_out, int out_size){
    const float* x    = (const float*)d_in[0];
    const void*  idx  = d_in[1];
    const float* w    = (const float*)d_in[2];
    const float* bias = (const float*)d_in[3];
    float* out = (float*)d_out;
    (void)in_sizes; (void)n_in; (void)out_size;

    cudaFuncSetAttribute(conv_main, cudaFuncAttributeMaxDynamicSharedMemorySize, SMEM_TOTAL);

    prep_idx_detect<<<148, 256>>>((const int*)idx);
    prep_xT<<<dim3(LL / 32, CIN / 32, NB), dim3(8, 32)>>>(x);
    prep_w<<<(COUT * KC + 255) / 256, 256>>>(w);
    conv_main<<<dim3(LL / BM, NB, COUT / BN), THREADS, SMEM_TOTAL>>>(idx, bias, out);
}